// round 6
// baseline (speedup 1.0000x reference)
#include <cuda_runtime.h>
#include <cuda_fp16.h>
#include <cstdint>
#include <math.h>

// ---------------- problem constants ----------------
constexpr int N_TOK  = 8192;
constexpr int QH     = 32;
constexpr int KH     = 2;
constexpr int G      = 16;
constexpr int D      = 128;
constexpr int KS     = 32;
constexpr int STRIDE = 16;
constexpr int M_BLK  = (N_TOK - KS) / STRIDE + 1;  // 511
constexpr float SM_SCALE = 0.08838834764831845f;

constexpr int NB      = 8;                  // tokens per CTA (2 per warp)
constexpr int NTILES  = 16;                 // m-tiles of 32 covering 512
constexpr int KF_U32  = NTILES * 2048;      // per kh: [tile][ni4][kp4][lane32][4]
constexpr int VF_U32  = NTILES * 2048;      // per kh: [tile][ni16][lane32][4]

// scratch (allocation-free rule: device globals)
__device__ float    g_ck [KH * M_BLK * D];
__device__ float    g_cv [KH * M_BLK * D];
__device__ uint32_t g_ckf[KH * KF_U32];     // QK B-fragments (half2, LDG.128-packed)
__device__ uint32_t g_cvf[KH * VF_U32];     // PV B-fragments (half2, LDG.128-packed)

__device__ __forceinline__ int mn_of(int n) {
    return (n >= KS - 1) ? ((n - (KS - 1)) / STRIDE + 1) : 0;
}
__device__ __forceinline__ uint32_t pack_h2(float a, float b) {
    __half2 h = __floats2half2_rn(a, b);
    return *reinterpret_cast<uint32_t*>(&h);
}
__device__ __forceinline__ void mma_16816(float* c,
                                          uint32_t a0, uint32_t a1, uint32_t a2, uint32_t a3,
                                          uint32_t b0, uint32_t b1) {
    asm volatile("mma.sync.aligned.m16n8k16.row.col.f32.f16.f16.f32 "
                 "{%0,%1,%2,%3}, {%4,%5,%6,%7}, {%8,%9}, {%0,%1,%2,%3};"
                 : "+f"(c[0]), "+f"(c[1]), "+f"(c[2]), "+f"(c[3])
                 : "r"(a0), "r"(a1), "r"(a2), "r"(a3), "r"(b0), "r"(b1));
}

// ---------------- kernel 1: compression ----------------
__global__ void __launch_bounds__(128) compress_kernel(
    const float* __restrict__ k, const float* __restrict__ v,
    const float* __restrict__ weight, const float* __restrict__ pe)
{
    const int m  = blockIdx.x;
    const int kh = blockIdx.y;
    const int d  = threadIdx.x;

    __shared__ float w_s[KS];
    __shared__ float wsum_s;
    if (threadIdx.x < KS) w_s[threadIdx.x] = weight[threadIdx.x];
    __syncthreads();
    if (threadIdx.x == 0) {
        float s = 0.f;
        #pragma unroll
        for (int i = 0; i < KS; i++) s += w_s[i];
        wsum_s = fmaxf(s, 1e-6f);
    }
    __syncthreads();

    float acck = 0.f, accv = 0.f;
    const int base = m * STRIDE;
    #pragma unroll 8
    for (int kk = 0; kk < KS; kk++) {
        const float w  = w_s[kk];
        const float pv = pe[kk * D + d];
        acck = fmaf(k[((size_t)(base + kk) * KH + kh) * D + d] + pv, w, acck);
        accv = fmaf(v[((size_t)(base + kk) * KH + kh) * D + d] + pv, w, accv);
    }
    const float inv = 1.0f / wsum_s;
    g_ck[((size_t)kh * M_BLK + m) * D + d] = acck * inv;
    g_cv[((size_t)kh * M_BLK + m) * D + d] = accv * inv;
}

// ---------------- kernel 2: pack fragments (LDG.128-friendly) ----------------
__global__ void __launch_bounds__(256) pack_kernel()
{
    const int i = blockIdx.x * 256 + threadIdx.x;
    if (i < KH * KF_U32) {
        // K frag: [kh][tile][ni(4)][kp(4)][lane(32)][q(4)] ; ki = kp*2 + (q>>1)
        const int q    = i & 3;
        const int lane = (i >> 2) & 31;
        const int kp   = (i >> 7) & 3;
        const int ni   = (i >> 9) & 3;
        const int tile = (i >> 11) & 15;
        const int kh   = (i >> 15) & 1;
        const int ki   = kp * 2 + (q >> 1);
        const int reg  = q & 1;
        const int m = tile * 32 + ni * 8 + (lane >> 2);
        const int d = ki * 16 + reg * 8 + (lane & 3) * 2;
        float2 f = make_float2(0.f, 0.f);
        if (m < M_BLK)
            f = *reinterpret_cast<const float2*>(&g_ck[((size_t)kh * M_BLK + m) * D + d]);
        g_ckf[i] = pack_h2(f.x, f.y);
    } else {
        // V frag: [kh][tile][ni(16)][lane(32)][q(4)] ; ki2 = q>>1 ; k-dim = m, n-dim = d
        const int j = i - KH * KF_U32;
        const int q    = j & 3;
        const int lane = (j >> 2) & 31;
        const int ni   = (j >> 7) & 15;
        const int tile = (j >> 11) & 15;
        const int kh   = (j >> 15) & 1;
        const int ki2  = q >> 1;
        const int reg  = q & 1;
        const int dn = ni * 8 + (lane >> 2);
        const int m  = tile * 32 + ki2 * 16 + reg * 8 + (lane & 3) * 2;
        float a = 0.f, b = 0.f;
        if (m < M_BLK)     a = g_cv[((size_t)kh * M_BLK + m) * D + dn];
        if (m + 1 < M_BLK) b = g_cv[((size_t)kh * M_BLK + m + 1) * D + dn];
        g_cvf[j] = pack_h2(a, b);
    }
}

// ---------------- kernel 3: HMMA flash attention, 2 tokens per warp ----------------
__global__ void __launch_bounds__(128) attn_mma(
    const float* __restrict__ q, float* __restrict__ out)
{
    const int bid   = blockIdx.x;
    const int kh    = bid & 1;
    const int chunk = bid >> 1;
    const int n0    = N_TOK - NB - chunk * NB;   // heavy tokens first

    const int tid  = threadIdx.x;
    const int w    = tid >> 5;
    const int lane = tid & 31;
    const int gid  = lane >> 2;
    const int tig  = lane & 3;

    const int n_t[2] = { n0 + 2 * w, n0 + 2 * w + 1 };
    const int Mn[2]  = { mn_of(n_t[0]), mn_of(n_t[1]) };
    const int Mn_max = Mn[1] > Mn[0] ? Mn[1] : Mn[0];

    // ---- Q A-fragments in registers (both tokens) ----
    uint32_t qf[2][8][4];
    #pragma unroll
    for (int tk = 0; tk < 2; tk++) {
        #pragma unroll
        for (int ki = 0; ki < 8; ki++) {
            #pragma unroll
            for (int reg = 0; reg < 4; reg++) {
                const int g = gid + 8 * (reg & 1);
                const int c = 16 * ki + 8 * (reg >> 1) + 2 * tig;
                const float2 f = *reinterpret_cast<const float2*>(
                    &q[(((size_t)n_t[tk] * QH) + kh * G + g) * D + c]);
                qf[tk][ki][reg] = pack_h2(f.x * SM_SCALE, f.y * SM_SCALE);
            }
        }
    }

    const uint32_t* kf = &g_ckf[(size_t)kh * KF_U32];
    const uint32_t* vf = &g_cvf[(size_t)kh * VF_U32];

    float oacc[2][16][4];
    #pragma unroll
    for (int tk = 0; tk < 2; tk++)
        #pragma unroll
        for (int a = 0; a < 16; a++)
            #pragma unroll
            for (int c = 0; c < 4; c++) oacc[tk][a][c] = 0.f;

    float rs[2][2] = {{0.f, 0.f}, {0.f, 0.f}};

    const int ntiles = (Mn_max + 31) >> 5;

    for (int t = 0; t < ntiles; t++) {
        const int m0 = t << 5;

        // ---- QK: S[2 x 16 x 32] ----
        float sacc[2][4][4];
        #pragma unroll
        for (int tk = 0; tk < 2; tk++)
            #pragma unroll
            for (int a = 0; a < 4; a++)
                #pragma unroll
                for (int c = 0; c < 4; c++) sacc[tk][a][c] = 0.f;

        #pragma unroll
        for (int kp = 0; kp < 4; kp++) {
            #pragma unroll
            for (int ni = 0; ni < 4; ni++) {
                const uint4 b = *reinterpret_cast<const uint4*>(
                    &kf[(((t * 4 + ni) * 4 + kp) << 7) + lane * 4]);
                mma_16816(sacc[0][ni], qf[0][2*kp][0],   qf[0][2*kp][1],   qf[0][2*kp][2],   qf[0][2*kp][3],   b.x, b.y);
                mma_16816(sacc[0][ni], qf[0][2*kp+1][0], qf[0][2*kp+1][1], qf[0][2*kp+1][2], qf[0][2*kp+1][3], b.z, b.w);
                mma_16816(sacc[1][ni], qf[1][2*kp][0],   qf[1][2*kp][1],   qf[1][2*kp][2],   qf[1][2*kp][3],   b.x, b.y);
                mma_16816(sacc[1][ni], qf[1][2*kp+1][0], qf[1][2*kp+1][1], qf[1][2*kp+1][2], qf[1][2*kp+1][3], b.z, b.w);
            }
        }

        // ---- softmax (fixed base), pack P into A-fragments ----
        uint32_t pf[2][2][4];
        #pragma unroll
        for (int tk = 0; tk < 2; tk++) {
            const int vcnt = Mn[tk] - m0;
            #pragma unroll
            for (int ni = 0; ni < 4; ni++) {
                const int col = ni * 8 + 2 * tig;
                const bool v0 = col     < vcnt;
                const bool v1 = col + 1 < vcnt;
                const float p0 = v0 ? __expf(sacc[tk][ni][0] - 5.0f) : 0.f;
                const float p1 = v1 ? __expf(sacc[tk][ni][1] - 5.0f) : 0.f;
                const float p2 = v0 ? __expf(sacc[tk][ni][2] - 5.0f) : 0.f;
                const float p3 = v1 ? __expf(sacc[tk][ni][3] - 5.0f) : 0.f;
                rs[tk][0] += p0 + p1;
                rs[tk][1] += p2 + p3;
                const int ki2 = ni >> 1, ch = ni & 1;
                pf[tk][ki2][0 + 2 * ch] = pack_h2(p0, p1);
                pf[tk][ki2][1 + 2 * ch] = pack_h2(p2, p3);
            }
        }

        // ---- PV: O[2 x 16 x 128] += P @ CV ----
        #pragma unroll
        for (int ni = 0; ni < 16; ni++) {
            const uint4 b = *reinterpret_cast<const uint4*>(
                &vf[((t * 16 + ni) << 7) + lane * 4]);
            mma_16816(oacc[0][ni], pf[0][0][0], pf[0][0][1], pf[0][0][2], pf[0][0][3], b.x, b.y);
            mma_16816(oacc[0][ni], pf[0][1][0], pf[0][1][1], pf[0][1][2], pf[0][1][3], b.z, b.w);
            mma_16816(oacc[1][ni], pf[1][0][0], pf[1][0][1], pf[1][0][2], pf[1][0][3], b.x, b.y);
            mma_16816(oacc[1][ni], pf[1][1][0], pf[1][1][1], pf[1][1][2], pf[1][1][3], b.z, b.w);
        }
    }

    // ---- epilogue ----
    #pragma unroll
    for (int tk = 0; tk < 2; tk++) {
        #pragma unroll
        for (int rh = 0; rh < 2; rh++) {
            float s = rs[tk][rh];
            s += __shfl_xor_sync(0xffffffffu, s, 1);
            s += __shfl_xor_sync(0xffffffffu, s, 2);
            const float inv = (Mn[tk] > 0) ? (1.0f / s) : 0.f;
            float* orow = &out[(((size_t)n_t[tk] * QH) + kh * G + gid + 8 * rh) * D];
            #pragma unroll
            for (int ni = 0; ni < 16; ni++) {
                float2 o;
                o.x = oacc[tk][ni][2 * rh + 0] * inv;
                o.y = oacc[tk][ni][2 * rh + 1] * inv;
                *reinterpret_cast<float2*>(&orow[ni * 8 + 2 * tig]) = o;
            }
        }
    }
}

// ---------------- launch ----------------
extern "C" void kernel_launch(void* const* d_in, const int* in_sizes, int n_in,
                              void* d_out, int out_size)
{
    const float* q  = (const float*)d_in[0];
    const float* k  = (const float*)d_in[1];
    const float* v  = (const float*)d_in[2];
    const float* w  = (const float*)d_in[3];
    const float* pe = (const float*)d_in[4];
    float* out = (float*)d_out;

    dim3 cgrid(M_BLK, KH);
    compress_kernel<<<cgrid, 128>>>(k, v, w, pe);
    pack_kernel<<<(KH * (KF_U32 + VF_U32)) / 256, 256>>>();
    attn_mma<<<(N_TOK / NB) * KH, 128>>>(q, out);
}

// round 7
// speedup vs baseline: 1.0303x; 1.0303x over previous
#include <cuda_runtime.h>
#include <cuda_fp16.h>
#include <cstdint>
#include <math.h>

// ---------------- problem constants ----------------
constexpr int N_TOK  = 8192;
constexpr int QH     = 32;
constexpr int KH     = 2;
constexpr int G      = 16;
constexpr int D      = 128;
constexpr int KS     = 32;
constexpr int STRIDE = 16;
constexpr int M_BLK  = (N_TOK - KS) / STRIDE + 1;  // 511
constexpr float SM_SCALE = 0.08838834764831845f;

constexpr int NB      = 4;                  // tokens per CTA (1 per warp)
constexpr int NTILES  = 16;                 // m-tiles of 32 covering 512
constexpr int KF_U32  = NTILES * 2048;      // per kh: [tile][ni4][kp4][lane32][4]
constexpr int VF_U32  = NTILES * 2048;      // per kh: [tile][ni16][lane32][4]

// scratch (allocation-free rule: device globals)
__device__ float    g_ck [KH * M_BLK * D];
__device__ float    g_cv [KH * M_BLK * D];
__device__ uint32_t g_ckf[KH * KF_U32];     // QK B-fragments (half2, LDG.128-packed)
__device__ uint32_t g_cvf[KH * VF_U32];     // PV B-fragments (half2, LDG.128-packed)

__device__ __forceinline__ int mn_of(int n) {
    return (n >= KS - 1) ? ((n - (KS - 1)) / STRIDE + 1) : 0;
}
__device__ __forceinline__ uint32_t pack_h2(float a, float b) {
    __half2 h = __floats2half2_rn(a, b);
    return *reinterpret_cast<uint32_t*>(&h);
}
__device__ __forceinline__ void mma_16816(float* c,
                                          uint32_t a0, uint32_t a1, uint32_t a2, uint32_t a3,
                                          uint32_t b0, uint32_t b1) {
    asm volatile("mma.sync.aligned.m16n8k16.row.col.f32.f16.f16.f32 "
                 "{%0,%1,%2,%3}, {%4,%5,%6,%7}, {%8,%9}, {%0,%1,%2,%3};"
                 : "+f"(c[0]), "+f"(c[1]), "+f"(c[2]), "+f"(c[3])
                 : "r"(a0), "r"(a1), "r"(a2), "r"(a3), "r"(b0), "r"(b1));
}

// ---------------- kernel 1: compression ----------------
__global__ void __launch_bounds__(128) compress_kernel(
    const float* __restrict__ k, const float* __restrict__ v,
    const float* __restrict__ weight, const float* __restrict__ pe)
{
    const int m  = blockIdx.x;
    const int kh = blockIdx.y;
    const int d  = threadIdx.x;

    __shared__ float w_s[KS];
    __shared__ float wsum_s;
    if (threadIdx.x < KS) w_s[threadIdx.x] = weight[threadIdx.x];
    __syncthreads();
    if (threadIdx.x == 0) {
        float s = 0.f;
        #pragma unroll
        for (int i = 0; i < KS; i++) s += w_s[i];
        wsum_s = fmaxf(s, 1e-6f);
    }
    __syncthreads();

    float acck = 0.f, accv = 0.f;
    const int base = m * STRIDE;
    #pragma unroll 8
    for (int kk = 0; kk < KS; kk++) {
        const float w  = w_s[kk];
        const float pv = pe[kk * D + d];
        acck = fmaf(k[((size_t)(base + kk) * KH + kh) * D + d] + pv, w, acck);
        accv = fmaf(v[((size_t)(base + kk) * KH + kh) * D + d] + pv, w, accv);
    }
    const float inv = 1.0f / wsum_s;
    g_ck[((size_t)kh * M_BLK + m) * D + d] = acck * inv;
    g_cv[((size_t)kh * M_BLK + m) * D + d] = accv * inv;
}

// ---------------- kernel 2: pack fragments (LDG.128-friendly) ----------------
__global__ void __launch_bounds__(256) pack_kernel()
{
    const int i = blockIdx.x * 256 + threadIdx.x;
    if (i < KH * KF_U32) {
        // K frag: [kh][tile(16)][ni(4)][kp(4)][lane(32)][q(4)] ; ki = kp*2 + (q>>1)
        const int q    = i & 3;
        const int lane = (i >> 2) & 31;
        const int kp   = (i >> 7) & 3;
        const int ni   = (i >> 9) & 3;
        const int tile = (i >> 11) & 15;
        const int kh   = (i >> 15) & 1;
        const int ki   = kp * 2 + (q >> 1);
        const int reg  = q & 1;
        const int m = tile * 32 + ni * 8 + (lane >> 2);
        const int d = ki * 16 + reg * 8 + (lane & 3) * 2;
        float2 f = make_float2(0.f, 0.f);
        if (m < M_BLK)
            f = *reinterpret_cast<const float2*>(&g_ck[((size_t)kh * M_BLK + m) * D + d]);
        g_ckf[i] = pack_h2(f.x, f.y);
    } else {
        // V frag: [kh][tile(16)][ni(16)][lane(32)][q(4)] ; ki2 = q>>1 ; k-dim = m, n-dim = d
        const int j = i - KH * KF_U32;
        const int q    = j & 3;
        const int lane = (j >> 2) & 31;
        const int ni   = (j >> 7) & 15;
        const int tile = (j >> 11) & 15;
        const int kh   = (j >> 15) & 1;
        const int ki2  = q >> 1;
        const int reg  = q & 1;
        const int dn = ni * 8 + (lane >> 2);
        const int m  = tile * 32 + ki2 * 16 + reg * 8 + (lane & 3) * 2;
        float a = 0.f, b = 0.f;
        if (m < M_BLK)     a = g_cv[((size_t)kh * M_BLK + m) * D + dn];
        if (m + 1 < M_BLK) b = g_cv[((size_t)kh * M_BLK + m + 1) * D + dn];
        g_cvf[j] = pack_h2(a, b);
    }
}

// ---------------- kernel 3: HMMA flash attention, warp-per-token, 64-m supertiles ----------------
__global__ void __launch_bounds__(128, 3) attn_mma(
    const float* __restrict__ q, float* __restrict__ out)
{
    const int bid   = blockIdx.x;
    const int kh    = bid & 1;
    const int chunk = bid >> 1;
    const int n0    = N_TOK - NB - chunk * NB;   // heavy tokens first

    const int tid  = threadIdx.x;
    const int w    = tid >> 5;
    const int lane = tid & 31;
    const int gid  = lane >> 2;
    const int tig  = lane & 3;

    const int n  = n0 + w;
    const int Mn = mn_of(n);

    if (Mn == 0) {
        #pragma unroll
        for (int rh = 0; rh < 2; rh++) {
            float* orow = &out[(((size_t)n * QH) + kh * G + gid + 8 * rh) * D];
            const float2 z = make_float2(0.f, 0.f);
            #pragma unroll
            for (int ni = 0; ni < 16; ni++)
                *reinterpret_cast<float2*>(&orow[ni * 8 + 2 * tig]) = z;
        }
        return;
    }

    // ---- Q A-fragments in registers (loaded once) ----
    uint32_t qf[8][4];
    #pragma unroll
    for (int ki = 0; ki < 8; ki++) {
        #pragma unroll
        for (int reg = 0; reg < 4; reg++) {
            const int g = gid + 8 * (reg & 1);
            const int c = 16 * ki + 8 * (reg >> 1) + 2 * tig;
            const float2 f = *reinterpret_cast<const float2*>(
                &q[(((size_t)n * QH) + kh * G + g) * D + c]);
            qf[ki][reg] = pack_h2(f.x * SM_SCALE, f.y * SM_SCALE);
        }
    }

    const uint32_t* kf = &g_ckf[(size_t)kh * KF_U32];
    const uint32_t* vf = &g_cvf[(size_t)kh * VF_U32];

    float oacc[16][4];
    #pragma unroll
    for (int a = 0; a < 16; a++)
        #pragma unroll
        for (int c = 0; c < 4; c++) oacc[a][c] = 0.f;

    float rs[2] = {0.f, 0.f};

    const int nsuper = (Mn + 63) >> 6;   // 64-m supertiles

    for (int t = 0; t < nsuper; t++) {

        // ---- QK for both 32-halves: S[2][4][4], 8 independent chains ----
        float sacc[2][4][4];
        #pragma unroll
        for (int h = 0; h < 2; h++)
            #pragma unroll
            for (int a = 0; a < 4; a++)
                #pragma unroll
                for (int c = 0; c < 4; c++) sacc[h][a][c] = 0.f;

        #pragma unroll
        for (int h = 0; h < 2; h++) {
            const int tt = 2 * t + h;
            #pragma unroll
            for (int kp = 0; kp < 4; kp++) {
                #pragma unroll
                for (int ni = 0; ni < 4; ni++) {
                    const uint4 b = *reinterpret_cast<const uint4*>(
                        &kf[(((tt * 4 + ni) * 4 + kp) << 7) + lane * 4]);
                    mma_16816(sacc[h][ni], qf[2*kp][0],   qf[2*kp][1],   qf[2*kp][2],   qf[2*kp][3],   b.x, b.y);
                    mma_16816(sacc[h][ni], qf[2*kp+1][0], qf[2*kp+1][1], qf[2*kp+1][2], qf[2*kp+1][3], b.z, b.w);
                }
            }
        }

        // ---- softmax (fixed base), pack P A-fragments for both halves ----
        uint32_t pf[2][2][4];
        #pragma unroll
        for (int h = 0; h < 2; h++) {
            const int vcnt = Mn - (t * 64 + h * 32);
            #pragma unroll
            for (int ni = 0; ni < 4; ni++) {
                const int col = ni * 8 + 2 * tig;
                const bool v0 = col     < vcnt;
                const bool v1 = col + 1 < vcnt;
                const float p0 = v0 ? __expf(sacc[h][ni][0] - 5.0f) : 0.f;
                const float p1 = v1 ? __expf(sacc[h][ni][1] - 5.0f) : 0.f;
                const float p2 = v0 ? __expf(sacc[h][ni][2] - 5.0f) : 0.f;
                const float p3 = v1 ? __expf(sacc[h][ni][3] - 5.0f) : 0.f;
                rs[0] += p0 + p1;
                rs[1] += p2 + p3;
                const int ki2 = ni >> 1, ch = ni & 1;
                pf[h][ki2][0 + 2 * ch] = pack_h2(p0, p1);
                pf[h][ki2][1 + 2 * ch] = pack_h2(p2, p3);
            }
        }

        // ---- PV for both halves: O += P @ CV ----
        #pragma unroll
        for (int h = 0; h < 2; h++) {
            const int tt = 2 * t + h;
            #pragma unroll
            for (int ni = 0; ni < 16; ni++) {
                const uint4 b = *reinterpret_cast<const uint4*>(
                    &vf[((tt * 16 + ni) << 7) + lane * 4]);
                mma_16816(oacc[ni], pf[h][0][0], pf[h][0][1], pf[h][0][2], pf[h][0][3], b.x, b.y);
                mma_16816(oacc[ni], pf[h][1][0], pf[h][1][1], pf[h][1][2], pf[h][1][3], b.z, b.w);
            }
        }
    }

    // ---- epilogue ----
    #pragma unroll
    for (int rh = 0; rh < 2; rh++) {
        float s = rs[rh];
        s += __shfl_xor_sync(0xffffffffu, s, 1);
        s += __shfl_xor_sync(0xffffffffu, s, 2);
        const float inv = 1.0f / s;
        float* orow = &out[(((size_t)n * QH) + kh * G + gid + 8 * rh) * D];
        #pragma unroll
        for (int ni = 0; ni < 16; ni++) {
            float2 o;
            o.x = oacc[ni][2 * rh + 0] * inv;
            o.y = oacc[ni][2 * rh + 1] * inv;
            *reinterpret_cast<float2*>(&orow[ni * 8 + 2 * tig]) = o;
        }
    }
}

// ---------------- launch ----------------
extern "C" void kernel_launch(void* const* d_in, const int* in_sizes, int n_in,
                              void* d_out, int out_size)
{
    const float* q  = (const float*)d_in[0];
    const float* k  = (const float*)d_in[1];
    const float* v  = (const float*)d_in[2];
    const float* w  = (const float*)d_in[3];
    const float* pe = (const float*)d_in[4];
    float* out = (float*)d_out;

    dim3 cgrid(M_BLK, KH);
    compress_kernel<<<cgrid, 128>>>(k, v, w, pe);
    pack_kernel<<<(KH * (KF_U32 + VF_U32)) / 256, 256>>>();
    attn_mma<<<(N_TOK / NB) * KH, 128>>>(q, out);
}

// round 8
// speedup vs baseline: 1.2625x; 1.2254x over previous
#include <cuda_runtime.h>
#include <cuda_fp16.h>
#include <cstdint>
#include <math.h>

// ---------------- problem constants ----------------
constexpr int N_TOK  = 8192;
constexpr int QH     = 32;
constexpr int KH     = 2;
constexpr int G      = 16;
constexpr int D      = 128;
constexpr int KS     = 32;
constexpr int STRIDE = 16;
constexpr int M_BLK  = (N_TOK - KS) / STRIDE + 1;  // 511
constexpr float SM_SCALE = 0.08838834764831845f;

constexpr int NB      = 4;                  // tokens per CTA (1 per warp)
constexpr int NTILES  = 16;                 // m-tiles of 32 covering 512
constexpr int KF_U32  = NTILES * 2048;      // per kh: [tile][ni4][kp4][lane32][4]
constexpr int VF_U32  = NTILES * 2048;      // per kh: [tile][ni16][lane32][4]

// scratch (allocation-free rule: device globals)
__device__ float    g_ck [KH * M_BLK * D];
__device__ float    g_cv [KH * M_BLK * D];
__device__ uint32_t g_ckf[KH * KF_U32];     // QK B-fragments (half2, LDG.128-packed)
__device__ uint32_t g_cvf[KH * VF_U32];     // PV B-fragments (half2, LDG.128-packed)

__device__ __forceinline__ int mn_of(int n) {
    return (n >= KS - 1) ? ((n - (KS - 1)) / STRIDE + 1) : 0;
}
__device__ __forceinline__ uint32_t pack_h2(float a, float b) {
    __half2 h = __floats2half2_rn(a, b);
    return *reinterpret_cast<uint32_t*>(&h);
}
__device__ __forceinline__ void mma_16816(float* c,
                                          uint32_t a0, uint32_t a1, uint32_t a2, uint32_t a3,
                                          uint32_t b0, uint32_t b1) {
    asm volatile("mma.sync.aligned.m16n8k16.row.col.f32.f16.f16.f32 "
                 "{%0,%1,%2,%3}, {%4,%5,%6,%7}, {%8,%9}, {%0,%1,%2,%3};"
                 : "+f"(c[0]), "+f"(c[1]), "+f"(c[2]), "+f"(c[3])
                 : "r"(a0), "r"(a1), "r"(a2), "r"(a3), "r"(b0), "r"(b1));
}

// ---------------- kernel 1: compression ----------------
__global__ void __launch_bounds__(128) compress_kernel(
    const float* __restrict__ k, const float* __restrict__ v,
    const float* __restrict__ weight, const float* __restrict__ pe)
{
    const int m  = blockIdx.x;
    const int kh = blockIdx.y;
    const int d  = threadIdx.x;

    __shared__ float w_s[KS];
    __shared__ float wsum_s;
    if (threadIdx.x < KS) w_s[threadIdx.x] = weight[threadIdx.x];
    __syncthreads();
    if (threadIdx.x == 0) {
        float s = 0.f;
        #pragma unroll
        for (int i = 0; i < KS; i++) s += w_s[i];
        wsum_s = fmaxf(s, 1e-6f);
    }
    __syncthreads();

    float acck = 0.f, accv = 0.f;
    const int base = m * STRIDE;
    #pragma unroll 8
    for (int kk = 0; kk < KS; kk++) {
        const float w  = w_s[kk];
        const float pv = pe[kk * D + d];
        acck = fmaf(k[((size_t)(base + kk) * KH + kh) * D + d] + pv, w, acck);
        accv = fmaf(v[((size_t)(base + kk) * KH + kh) * D + d] + pv, w, accv);
    }
    const float inv = 1.0f / wsum_s;
    g_ck[((size_t)kh * M_BLK + m) * D + d] = acck * inv;
    g_cv[((size_t)kh * M_BLK + m) * D + d] = accv * inv;
}

// ---------------- kernel 2: pack fragments (LDG.128-friendly) ----------------
__global__ void __launch_bounds__(256) pack_kernel()
{
    const int i = blockIdx.x * 256 + threadIdx.x;
    if (i < KH * KF_U32) {
        // K frag: [kh][tile(16)][ni(4)][kp(4)][lane(32)][q(4)] ; ki = kp*2 + (q>>1)
        const int q    = i & 3;
        const int lane = (i >> 2) & 31;
        const int kp   = (i >> 7) & 3;
        const int ni   = (i >> 9) & 3;
        const int tile = (i >> 11) & 15;
        const int kh   = (i >> 15) & 1;
        const int ki   = kp * 2 + (q >> 1);
        const int reg  = q & 1;
        const int m = tile * 32 + ni * 8 + (lane >> 2);
        const int d = ki * 16 + reg * 8 + (lane & 3) * 2;
        float2 f = make_float2(0.f, 0.f);
        if (m < M_BLK)
            f = *reinterpret_cast<const float2*>(&g_ck[((size_t)kh * M_BLK + m) * D + d]);
        g_ckf[i] = pack_h2(f.x, f.y);
    } else {
        // V frag: [kh][tile(16)][ni(16)][lane(32)][q(4)] ; ki2 = q>>1 ; k-dim = m, n-dim = d
        const int j = i - KH * KF_U32;
        const int q    = j & 3;
        const int lane = (j >> 2) & 31;
        const int ni   = (j >> 7) & 15;
        const int tile = (j >> 11) & 15;
        const int kh   = (j >> 15) & 1;
        const int ki2  = q >> 1;
        const int reg  = q & 1;
        const int dn = ni * 8 + (lane >> 2);
        const int m  = tile * 32 + ki2 * 16 + reg * 8 + (lane & 3) * 2;
        float a = 0.f, b = 0.f;
        if (m < M_BLK)     a = g_cv[((size_t)kh * M_BLK + m) * D + dn];
        if (m + 1 < M_BLK) b = g_cv[((size_t)kh * M_BLK + m + 1) * D + dn];
        g_cvf[j] = pack_h2(a, b);
    }
}

// ---------------- kernel 3: HMMA flash attention, warp-per-token, qf in smem ----------------
__global__ void __launch_bounds__(128, 4) attn_mma(
    const float* __restrict__ q, float* __restrict__ out)
{
    const int bid   = blockIdx.x;
    const int kh    = bid & 1;
    const int chunk = bid >> 1;
    const int n0    = N_TOK - NB - chunk * NB;   // heavy tokens first

    const int tid  = threadIdx.x;
    const int w    = tid >> 5;
    const int lane = tid & 31;
    const int gid  = lane >> 2;
    const int tig  = lane & 3;

    const int n  = n0 + w;
    const int Mn = mn_of(n);

    if (Mn == 0) {
        #pragma unroll
        for (int rh = 0; rh < 2; rh++) {
            float* orow = &out[(((size_t)n * QH) + kh * G + gid + 8 * rh) * D];
            const float2 z = make_float2(0.f, 0.f);
            #pragma unroll
            for (int ni = 0; ni < 16; ni++)
                *reinterpret_cast<float2*>(&orow[ni * 8 + 2 * tig]) = z;
        }
        return;
    }

    // ---- stage Q A-fragments into warp-private smem (4 KB/warp) ----
    // layout per warp: [ki(8)][lane(32)][reg(4)] u32 ; LDS.128 per (ki,lane) is
    // conflict-free (8 lanes per 128B phase cover all 32 banks).
    __shared__ uint32_t qsm[NB * 1024];
    uint32_t* myq = &qsm[w * 1024];
    #pragma unroll
    for (int ki = 0; ki < 8; ki++) {
        #pragma unroll
        for (int reg = 0; reg < 4; reg++) {
            const int g = gid + 8 * (reg & 1);
            const int c = 16 * ki + 8 * (reg >> 1) + 2 * tig;
            const float2 f = *reinterpret_cast<const float2*>(
                &q[(((size_t)n * QH) + kh * G + g) * D + c]);
            myq[ki * 128 + lane * 4 + reg] = pack_h2(f.x * SM_SCALE, f.y * SM_SCALE);
        }
    }
    __syncwarp();

    const uint32_t* kf = &g_ckf[(size_t)kh * KF_U32];
    const uint32_t* vf = &g_cvf[(size_t)kh * VF_U32];

    float oacc[16][4];
    #pragma unroll
    for (int a = 0; a < 16; a++)
        #pragma unroll
        for (int c = 0; c < 4; c++) oacc[a][c] = 0.f;

    float rs[2] = {0.f, 0.f};

    const int ntiles = (Mn + 31) >> 5;

    for (int t = 0; t < ntiles; t++) {
        const int m0 = t << 5;

        // ---- QK: S[16 x 32] ----
        float sacc[4][4];
        #pragma unroll
        for (int a = 0; a < 4; a++)
            #pragma unroll
            for (int c = 0; c < 4; c++) sacc[a][c] = 0.f;

        #pragma unroll
        for (int kp = 0; kp < 4; kp++) {
            const uint4 a0 = *reinterpret_cast<const uint4*>(&myq[(2 * kp    ) * 128 + lane * 4]);
            const uint4 a1 = *reinterpret_cast<const uint4*>(&myq[(2 * kp + 1) * 128 + lane * 4]);
            #pragma unroll
            for (int ni = 0; ni < 4; ni++) {
                const uint4 b = *reinterpret_cast<const uint4*>(
                    &kf[(((t * 4 + ni) * 4 + kp) << 7) + lane * 4]);
                mma_16816(sacc[ni], a0.x, a0.y, a0.z, a0.w, b.x, b.y);
                mma_16816(sacc[ni], a1.x, a1.y, a1.z, a1.w, b.z, b.w);
            }
        }

        // ---- softmax (fixed base), pack P into A-fragments ----
        const int vcnt = Mn - m0;
        uint32_t pf[2][4];
        #pragma unroll
        for (int ni = 0; ni < 4; ni++) {
            const int col = ni * 8 + 2 * tig;
            const bool v0 = col     < vcnt;
            const bool v1 = col + 1 < vcnt;
            const float p0 = v0 ? __expf(sacc[ni][0] - 5.0f) : 0.f;
            const float p1 = v1 ? __expf(sacc[ni][1] - 5.0f) : 0.f;
            const float p2 = v0 ? __expf(sacc[ni][2] - 5.0f) : 0.f;
            const float p3 = v1 ? __expf(sacc[ni][3] - 5.0f) : 0.f;
            rs[0] += p0 + p1;
            rs[1] += p2 + p3;
            const int ki2 = ni >> 1, ch = ni & 1;
            pf[ki2][0 + 2 * ch] = pack_h2(p0, p1);
            pf[ki2][1 + 2 * ch] = pack_h2(p2, p3);
        }

        // ---- PV: O[16 x 128] += P @ CV ----
        #pragma unroll
        for (int ni = 0; ni < 16; ni++) {
            const uint4 b = *reinterpret_cast<const uint4*>(
                &vf[((t * 16 + ni) << 7) + lane * 4]);
            mma_16816(oacc[ni], pf[0][0], pf[0][1], pf[0][2], pf[0][3], b.x, b.y);
            mma_16816(oacc[ni], pf[1][0], pf[1][1], pf[1][2], pf[1][3], b.z, b.w);
        }
    }

    // ---- epilogue ----
    #pragma unroll
    for (int rh = 0; rh < 2; rh++) {
        float s = rs[rh];
        s += __shfl_xor_sync(0xffffffffu, s, 1);
        s += __shfl_xor_sync(0xffffffffu, s, 2);
        const float inv = 1.0f / s;
        float* orow = &out[(((size_t)n * QH) + kh * G + gid + 8 * rh) * D];
        #pragma unroll
        for (int ni = 0; ni < 16; ni++) {
            float2 o;
            o.x = oacc[ni][2 * rh + 0] * inv;
            o.y = oacc[ni][2 * rh + 1] * inv;
            *reinterpret_cast<float2*>(&orow[ni * 8 + 2 * tig]) = o;
        }
    }
}

// ---------------- launch ----------------
extern "C" void kernel_launch(void* const* d_in, const int* in_sizes, int n_in,
                              void* d_out, int out_size)
{
    const float* q  = (const float*)d_in[0];
    const float* k  = (const float*)d_in[1];
    const float* v  = (const float*)d_in[2];
    const float* w  = (const float*)d_in[3];
    const float* pe = (const float*)d_in[4];
    float* out = (float*)d_out;

    dim3 cgrid(M_BLK, KH);
    compress_kernel<<<cgrid, 128>>>(k, v, w, pe);
    pack_kernel<<<(KH * (KF_U32 + VF_U32)) / 256, 256>>>();
    attn_mma<<<(N_TOK / NB) * KH, 128>>>(q, out);
}

// round 9
// speedup vs baseline: 1.4011x; 1.1097x over previous
#include <cuda_runtime.h>
#include <cuda_fp16.h>
#include <cstdint>
#include <math.h>

// ---------------- problem constants ----------------
constexpr int N_TOK  = 8192;
constexpr int QH     = 32;
constexpr int KH     = 2;
constexpr int G      = 16;
constexpr int D      = 128;
constexpr int KS     = 32;
constexpr int STRIDE = 16;
constexpr int M_BLK  = (N_TOK - KS) / STRIDE + 1;  // 511
constexpr float SM_SCALE = 0.08838834764831845f;

constexpr int NB      = 4;                  // tokens per CTA (1 per warp)
constexpr int NTILES  = 16;                 // m-tiles of 32 covering 512
constexpr int KF_U32  = NTILES * 2048;      // per kh: [tile][ni4][kp4][lane32][4]
constexpr int VF_U32  = NTILES * 2048;      // per kh: [tile][ni16][lane32][4]

// scratch (allocation-free rule: device globals)
__device__ float    g_ck [KH * M_BLK * D];
__device__ float    g_cv [KH * M_BLK * D];
__device__ uint32_t g_ckf[KH * KF_U32];     // QK B-fragments (half2, LDG.128-packed)
__device__ uint32_t g_cvf[KH * VF_U32];     // PV B-fragments (half2, LDG.128-packed)

__device__ __forceinline__ int mn_of(int n) {
    return (n >= KS - 1) ? ((n - (KS - 1)) / STRIDE + 1) : 0;
}
__device__ __forceinline__ uint32_t pack_h2(float a, float b) {
    __half2 h = __floats2half2_rn(a, b);
    return *reinterpret_cast<uint32_t*>(&h);
}
__device__ __forceinline__ uint32_t smem_u32(const void* p) {
    uint32_t a;
    asm("{ .reg .u64 t; cvta.to.shared.u64 t, %1; cvt.u32.u64 %0, t; }" : "=r"(a) : "l"(p));
    return a;
}
__device__ __forceinline__ void cp_async16(uint32_t saddr, const void* gaddr) {
    asm volatile("cp.async.cg.shared.global [%0], [%1], 16;" :: "r"(saddr), "l"(gaddr));
}
__device__ __forceinline__ void cp_commit() {
    asm volatile("cp.async.commit_group;");
}
template <int N>
__device__ __forceinline__ void cp_wait() {
    asm volatile("cp.async.wait_group %0;" :: "n"(N));
}
__device__ __forceinline__ void mma_16816(float* c,
                                          uint32_t a0, uint32_t a1, uint32_t a2, uint32_t a3,
                                          uint32_t b0, uint32_t b1) {
    asm volatile("mma.sync.aligned.m16n8k16.row.col.f32.f16.f16.f32 "
                 "{%0,%1,%2,%3}, {%4,%5,%6,%7}, {%8,%9}, {%0,%1,%2,%3};"
                 : "+f"(c[0]), "+f"(c[1]), "+f"(c[2]), "+f"(c[3])
                 : "r"(a0), "r"(a1), "r"(a2), "r"(a3), "r"(b0), "r"(b1));
}

// ---------------- kernel 1: compression ----------------
__global__ void __launch_bounds__(128) compress_kernel(
    const float* __restrict__ k, const float* __restrict__ v,
    const float* __restrict__ weight, const float* __restrict__ pe)
{
    const int m  = blockIdx.x;
    const int kh = blockIdx.y;
    const int d  = threadIdx.x;

    __shared__ float w_s[KS];
    __shared__ float wsum_s;
    if (threadIdx.x < KS) w_s[threadIdx.x] = weight[threadIdx.x];
    __syncthreads();
    if (threadIdx.x == 0) {
        float s = 0.f;
        #pragma unroll
        for (int i = 0; i < KS; i++) s += w_s[i];
        wsum_s = fmaxf(s, 1e-6f);
    }
    __syncthreads();

    float acck = 0.f, accv = 0.f;
    const int base = m * STRIDE;
    #pragma unroll 8
    for (int kk = 0; kk < KS; kk++) {
        const float w  = w_s[kk];
        const float pv = pe[kk * D + d];
        acck = fmaf(k[((size_t)(base + kk) * KH + kh) * D + d] + pv, w, acck);
        accv = fmaf(v[((size_t)(base + kk) * KH + kh) * D + d] + pv, w, accv);
    }
    const float inv = 1.0f / wsum_s;
    g_ck[((size_t)kh * M_BLK + m) * D + d] = acck * inv;
    g_cv[((size_t)kh * M_BLK + m) * D + d] = accv * inv;
}

// ---------------- kernel 2: pack fragments (LDG.128-friendly) ----------------
__global__ void __launch_bounds__(256) pack_kernel()
{
    const int i = blockIdx.x * 256 + threadIdx.x;
    if (i < KH * KF_U32) {
        // K frag: [kh][tile(16)][ni(4)][kp(4)][lane(32)][q(4)] ; ki = kp*2 + (q>>1)
        const int q    = i & 3;
        const int lane = (i >> 2) & 31;
        const int kp   = (i >> 7) & 3;
        const int ni   = (i >> 9) & 3;
        const int tile = (i >> 11) & 15;
        const int kh   = (i >> 15) & 1;
        const int ki   = kp * 2 + (q >> 1);
        const int reg  = q & 1;
        const int m = tile * 32 + ni * 8 + (lane >> 2);
        const int d = ki * 16 + reg * 8 + (lane & 3) * 2;
        float2 f = make_float2(0.f, 0.f);
        if (m < M_BLK)
            f = *reinterpret_cast<const float2*>(&g_ck[((size_t)kh * M_BLK + m) * D + d]);
        g_ckf[i] = pack_h2(f.x, f.y);
    } else {
        // V frag: [kh][tile(16)][ni(16)][lane(32)][q(4)] ; ki2 = q>>1 ; k-dim = m, n-dim = d
        const int j = i - KH * KF_U32;
        const int q    = j & 3;
        const int lane = (j >> 2) & 31;
        const int ni   = (j >> 7) & 15;
        const int tile = (j >> 11) & 15;
        const int kh   = (j >> 15) & 1;
        const int ki2  = q >> 1;
        const int reg  = q & 1;
        const int dn = ni * 8 + (lane >> 2);
        const int m  = tile * 32 + ki2 * 16 + reg * 8 + (lane & 3) * 2;
        float a = 0.f, b = 0.f;
        if (m < M_BLK)     a = g_cv[((size_t)kh * M_BLK + m) * D + dn];
        if (m + 1 < M_BLK) b = g_cv[((size_t)kh * M_BLK + m + 1) * D + dn];
        g_cvf[j] = pack_h2(a, b);
    }
}

// ---------------- kernel 3: HMMA flash attention, cp.async double-buffered ----------------
__global__ void __launch_bounds__(128, 4) attn_mma(
    const float* __restrict__ q, float* __restrict__ out)
{
    const int bid   = blockIdx.x;
    const int kh    = bid & 1;
    const int chunk = bid >> 1;
    const int n0    = N_TOK - NB - chunk * NB;   // heavy tokens first

    const int tid  = threadIdx.x;
    const int w    = tid >> 5;
    const int lane = tid & 31;
    const int gid  = lane >> 2;
    const int tig  = lane & 3;

    const int n      = n0 + w;
    const int Mn     = mn_of(n);
    const int Mn_max = mn_of(n0 + NB - 1);   // uniform per CTA

    if (Mn_max == 0) {
        #pragma unroll
        for (int rh = 0; rh < 2; rh++) {
            float* orow = &out[(((size_t)n * QH) + kh * G + gid + 8 * rh) * D];
            const float2 z = make_float2(0.f, 0.f);
            #pragma unroll
            for (int ni = 0; ni < 16; ni++)
                *reinterpret_cast<float2*>(&orow[ni * 8 + 2 * tig]) = z;
        }
        return;
    }

    // smem: qf (16 KB) + double-buffered K/V frag tiles (2 x 16 KB) = 48 KB
    __shared__ uint32_t qsm[NB * 1024];
    __shared__ uint32_t kbuf[2][2048];
    __shared__ uint32_t vbuf[2][2048];

    const uint32_t* kf = &g_ckf[(size_t)kh * KF_U32];
    const uint32_t* vf = &g_cvf[(size_t)kh * VF_U32];

    const int ntiles = (Mn_max + 31) >> 5;

    // ---- prefetch tile 0 (all threads) ----
    {
        const uint32_t sk = smem_u32(&kbuf[0][0]) + tid * 16;
        const uint32_t sv = smem_u32(&vbuf[0][0]) + tid * 16;
        #pragma unroll
        for (int i = 0; i < 4; i++) {
            cp_async16(sk + i * 2048, kf + tid * 4 + i * 512);
            cp_async16(sv + i * 2048, vf + tid * 4 + i * 512);
        }
        cp_commit();
    }

    // ---- stage Q A-fragments into warp-private smem (overlaps prefetch) ----
    uint32_t* myq = &qsm[w * 1024];
    #pragma unroll
    for (int ki = 0; ki < 8; ki++) {
        #pragma unroll
        for (int reg = 0; reg < 4; reg++) {
            const int g = gid + 8 * (reg & 1);
            const int c = 16 * ki + 8 * (reg >> 1) + 2 * tig;
            const float2 f = *reinterpret_cast<const float2*>(
                &q[(((size_t)n * QH) + kh * G + g) * D + c]);
            myq[ki * 128 + lane * 4 + reg] = pack_h2(f.x * SM_SCALE, f.y * SM_SCALE);
        }
    }

    float oacc[16][4];
    #pragma unroll
    for (int a = 0; a < 16; a++)
        #pragma unroll
        for (int c = 0; c < 4; c++) oacc[a][c] = 0.f;

    float rs[2] = {0.f, 0.f};

    for (int t = 0; t < ntiles; t++) {
        // prefetch next tile into alternate buffer, then wait for current
        if (t + 1 < ntiles) {
            const int nb = (t + 1) & 1;
            const uint32_t sk = smem_u32(&kbuf[nb][0]) + tid * 16;
            const uint32_t sv = smem_u32(&vbuf[nb][0]) + tid * 16;
            const uint32_t* gk = kf + (t + 1) * 2048;
            const uint32_t* gv = vf + (t + 1) * 2048;
            #pragma unroll
            for (int i = 0; i < 4; i++) {
                cp_async16(sk + i * 2048, gk + tid * 4 + i * 512);
                cp_async16(sv + i * 2048, gv + tid * 4 + i * 512);
            }
            cp_commit();
            cp_wait<1>();
        } else {
            cp_wait<0>();
        }
        __syncthreads();   // current buffer fully staged for all warps

        const uint32_t* kb = &kbuf[t & 1][0];
        const uint32_t* vb = &vbuf[t & 1][0];

        // ---- QK: S[16 x 32] ----
        float sacc[4][4];
        #pragma unroll
        for (int a = 0; a < 4; a++)
            #pragma unroll
            for (int c = 0; c < 4; c++) sacc[a][c] = 0.f;

        #pragma unroll
        for (int kp = 0; kp < 4; kp++) {
            const uint4 a0 = *reinterpret_cast<const uint4*>(&myq[(2 * kp    ) * 128 + lane * 4]);
            const uint4 a1 = *reinterpret_cast<const uint4*>(&myq[(2 * kp + 1) * 128 + lane * 4]);
            #pragma unroll
            for (int ni = 0; ni < 4; ni++) {
                const uint4 b = *reinterpret_cast<const uint4*>(&kb[((ni * 4 + kp) << 7) + lane * 4]);
                mma_16816(sacc[ni], a0.x, a0.y, a0.z, a0.w, b.x, b.y);
                mma_16816(sacc[ni], a1.x, a1.y, a1.z, a1.w, b.z, b.w);
            }
        }

        // ---- softmax (fixed base), pack P into A-fragments ----
        const int vcnt = Mn - (t << 5);
        uint32_t pf[2][4];
        #pragma unroll
        for (int ni = 0; ni < 4; ni++) {
            const int col = ni * 8 + 2 * tig;
            const bool v0 = col     < vcnt;
            const bool v1 = col + 1 < vcnt;
            const float p0 = v0 ? __expf(sacc[ni][0] - 5.0f) : 0.f;
            const float p1 = v1 ? __expf(sacc[ni][1] - 5.0f) : 0.f;
            const float p2 = v0 ? __expf(sacc[ni][2] - 5.0f) : 0.f;
            const float p3 = v1 ? __expf(sacc[ni][3] - 5.0f) : 0.f;
            rs[0] += p0 + p1;
            rs[1] += p2 + p3;
            const int ki2 = ni >> 1, ch = ni & 1;
            pf[ki2][0 + 2 * ch] = pack_h2(p0, p1);
            pf[ki2][1 + 2 * ch] = pack_h2(p2, p3);
        }

        // ---- PV: O[16 x 128] += P @ CV ----
        #pragma unroll
        for (int ni = 0; ni < 16; ni++) {
            const uint4 b = *reinterpret_cast<const uint4*>(&vb[(ni << 7) + lane * 4]);
            mma_16816(oacc[ni], pf[0][0], pf[0][1], pf[0][2], pf[0][3], b.x, b.y);
            mma_16816(oacc[ni], pf[1][0], pf[1][1], pf[1][2], pf[1][3], b.z, b.w);
        }

        __syncthreads();   // all warps done with this buffer before it's re-staged
    }

    // ---- epilogue ----
    #pragma unroll
    for (int rh = 0; rh < 2; rh++) {
        float s = rs[rh];
        s += __shfl_xor_sync(0xffffffffu, s, 1);
        s += __shfl_xor_sync(0xffffffffu, s, 2);
        const float inv = (Mn > 0) ? (1.0f / s) : 0.f;
        float* orow = &out[(((size_t)n * QH) + kh * G + gid + 8 * rh) * D];
        #pragma unroll
        for (int ni = 0; ni < 16; ni++) {
            float2 o;
            o.x = oacc[ni][2 * rh + 0] * inv;
            o.y = oacc[ni][2 * rh + 1] * inv;
            *reinterpret_cast<float2*>(&orow[ni * 8 + 2 * tig]) = o;
        }
    }
}

// ---------------- launch ----------------
extern "C" void kernel_launch(void* const* d_in, const int* in_sizes, int n_in,
                              void* d_out, int out_size)
{
    const float* q  = (const float*)d_in[0];
    const float* k  = (const float*)d_in[1];
    const float* v  = (const float*)d_in[2];
    const float* w  = (const float*)d_in[3];
    const float* pe = (const float*)d_in[4];
    float* out = (float*)d_out;

    dim3 cgrid(M_BLK, KH);
    compress_kernel<<<cgrid, 128>>>(k, v, w, pe);
    pack_kernel<<<(KH * (KF_U32 + VF_U32)) / 256, 256>>>();
    attn_mma<<<(N_TOK / NB) * KH, 128>>>(q, out);
}